// round 2
// baseline (speedup 1.0000x reference)
#include <cuda_runtime.h>

// ---------------------------------------------------------------------------
// PatternBranch fused kernel.
//
// reference:
//   feats0 = relu(conv3x3_s2_SAME(inputs, conv_w) + conv_b)   [B,32,32,128]
//   feats1 = mean_hw(feats0)                                  [B,128]
//   matches = feats1 @ match_w + match_b > 0
//   p = sigmoid( gather(feats0, psi, ch).flat @ pat_w + pat_b )
//   cat = [p, (1-p)/2, (1-p)/2]
//   base = softmax(feats0.flat @ base_w + base_b)
//   out = where(matches & p>=0.5, cat, base)
//
// Everything downstream of feats0 is linear -> fuse into 5 scalar
// accumulators per sample; feats0 is never materialized.
//
// SAME padding for in=64, k=3, s=2: pad_low = 0, pad_high = 1.
// input row/col index = 2*o + k, zero when >= 64.
// ---------------------------------------------------------------------------

#define SPC 4   // samples per CTA (2 f32x2 pairs)

// scratch (no allocations allowed)
__device__ float4 g_EW[1024 * 128];   // per-(pos,channel): base_w0..2, pat weight
__device__ float  g_acc[256 * 5];     // per-sample: match, pat, base0..2

static __device__ __forceinline__ unsigned long long pack2(float x) {
    unsigned long long r;
    asm("mov.b64 %0, {%1, %1};" : "=l"(r) : "f"(x));
    return r;
}
static __device__ __forceinline__ void fma2(unsigned long long& d,
                                            unsigned long long a,
                                            unsigned long long b) {
    // packed f32x2: d.lo = a.lo*b.lo + d.lo ; d.hi = a.hi*b.hi + d.hi
    asm("fma.rn.f32x2 %0, %1, %2, %0;" : "+l"(d) : "l"(a), "l"(b));
}
static __device__ __forceinline__ void unpack2(unsigned long long v,
                                               float& lo, float& hi) {
    asm("mov.b64 {%0, %1}, %2;" : "=f"(lo), "=f"(hi) : "l"(v));
}

// ---------------------------------------------------------------------------
// Prologue: build fused epilogue-weight table, zero accumulators.
// grid 1024 (positions), block 128 (channels)
// ---------------------------------------------------------------------------
__global__ void prep_kernel(const float* __restrict__ base_w,
                            const float* __restrict__ pat_w,
                            const int*   __restrict__ psi) {
    const int pos = blockIdx.x;
    const int c   = threadIdx.x;

    __shared__ int   s_idx[32];
    __shared__ float s_pw[32];
    if (c < 32) {
        s_idx[c] = psi[c];
        s_pw[c]  = pat_w[pos * 32 + c];
    }
    __syncthreads();

    float pw = 0.f;
#pragma unroll
    for (int k = 0; k < 32; k++)
        if (s_idx[k] == c) pw += s_pw[k];

    const float* bw = base_w + ((size_t)(pos * 128 + c)) * 3;
    g_EW[pos * 128 + c] = make_float4(bw[0], bw[1], bw[2], pw);

    if (pos == 0) {
        for (int i = c; i < 256 * 5; i += 128) g_acc[i] = 0.f;
    }
}

// ---------------------------------------------------------------------------
// Main fused conv + reductions.
// grid (8 row-blocks, 64 sample-groups), block 128 (lane = channel)
// CTA covers: 4 output rows x 32 cols x 128 ch x 4 samples.
// ---------------------------------------------------------------------------
__global__ __launch_bounds__(128)
void main_kernel(const float* __restrict__ in,
                 const float* __restrict__ conv_w,
                 const float* __restrict__ conv_b,
                 const float* __restrict__ match_w) {
    // staged inputs: [r:9][q:195 = col(0..64)*3+ci][s:4], sample-minor so one
    // 16B broadcast LDS yields 4 samples (= 2 f32x2 pairs). 28080 B.
    __shared__ __align__(16) float s_in[9 * 195 * SPC];

    const int tid     = threadIdx.x;
    const int bx      = blockIdx.x;        // output-row block (4 rows each)
    const int b0      = blockIdx.y * SPC;  // first sample
    const int rowBase = bx * 8;            // first input row of the window

    // zero the col-64 padding slots (input col 64 is SAME-padding)
    if (tid < 108) {
        int s = tid & 3;
        int t = tid >> 2;        // 0..26 = r*3+ci
        int r = t / 3, ci = t % 3;
        s_in[(r * 195 + 192 + ci) * 4 + s] = 0.f;
    }
    // stage 9 input rows x 64 cols x 3 ch x 4 samples
    for (int i = tid; i < 9 * 192 * SPC; i += 128) {
        int s = i & 3;
        int t = i >> 2;
        int q = t % 192;           // col*3 + ci
        int r = t / 192;
        int rin = rowBase + r;
        float v = 0.f;
        if (rin < 64) v = in[(size_t)(b0 + s) * 12288 + rin * 192 + q];
        s_in[(r * 195 + q) * 4 + s] = v;
    }

    const int c = tid;  // this lane's output channel
    const float mw = match_w[c];
    const unsigned long long cbp = pack2(conv_b[c]);

    unsigned long long wp[27];   // conv weights packed {w,w}
#pragma unroll
    for (int t = 0; t < 27; t++) wp[t] = pack2(conv_w[t * 128 + c]);

    float accM[SPC], accP[SPC], accB0[SPC], accB1[SPC], accB2[SPC];
#pragma unroll
    for (int s = 0; s < SPC; s++) {
        accM[s] = 0.f; accP[s] = 0.f;
        accB0[s] = 0.f; accB1[s] = 0.f; accB2[s] = 0.f;
    }

    __syncthreads();

    for (int ohl = 0; ohl < 4; ohl++) {
        for (int ow = 0; ow < 32; ow++) {
            unsigned long long a0 = cbp, a1 = cbp;  // conv accum (2 pairs)
            const float* bp = s_in + ow * 24;       // (2*ow)*3*4 floats
#pragma unroll
            for (int kh = 0; kh < 3; kh++) {
#pragma unroll
                for (int kw = 0; kw < 3; kw++) {
#pragma unroll
                    for (int ci = 0; ci < 3; ci++) {
                        const int t = (kh * 3 + kw) * 3 + ci;
                        const int r = 2 * ohl + kh;
                        ulonglong2 v = *reinterpret_cast<const ulonglong2*>(
                            bp + (r * 195 + kw * 3 + ci) * 4);
                        fma2(a0, v.x, wp[t]);
                        fma2(a1, v.y, wp[t]);
                    }
                }
            }
            const int pos = (bx * 4 + ohl) * 32 + ow;
            const float4 ew = g_EW[pos * 128 + c];
            float f[4];
            unpack2(a0, f[0], f[1]);
            unpack2(a1, f[2], f[3]);
#pragma unroll
            for (int s = 0; s < 4; s++) {
                const float x = fmaxf(f[s], 0.f);      // relu(conv+bias)
                accM[s]  = fmaf(x, mw,   accM[s]);
                accB0[s] = fmaf(x, ew.x, accB0[s]);
                accB1[s] = fmaf(x, ew.y, accB1[s]);
                accB2[s] = fmaf(x, ew.z, accB2[s]);
                accP[s]  = fmaf(x, ew.w, accP[s]);
            }
        }
    }

    // reduce over channels (lanes) and accumulate globally
    const int lane = tid & 31;
#pragma unroll
    for (int s = 0; s < SPC; s++) {
        float v[5] = {accM[s], accP[s], accB0[s], accB1[s], accB2[s]};
#pragma unroll
        for (int j = 0; j < 5; j++) {
            float x = v[j];
#pragma unroll
            for (int o = 16; o > 0; o >>= 1)
                x += __shfl_down_sync(0xffffffffu, x, o);
            if (lane == 0) atomicAdd(&g_acc[(b0 + s) * 5 + j], x);
        }
    }
}

// ---------------------------------------------------------------------------
// Finalize: per-sample sigmoid / softmax / routing.
// ---------------------------------------------------------------------------
__global__ void finalize_kernel(const float* __restrict__ match_b,
                                const float* __restrict__ pat_b,
                                const float* __restrict__ base_b,
                                float* __restrict__ out) {
    const int b = threadIdx.x;
    if (b >= 256) return;
    const float* a = g_acc + b * 5;

    const bool matched = (a[0] * (1.f / 1024.f) + match_b[0]) > 0.f;

    const float plog = a[1] + pat_b[0];
    const float p = 1.f / (1.f + expf(-plog));

    const float l0 = a[2] + base_b[0];
    const float l1 = a[3] + base_b[1];
    const float l2 = a[4] + base_b[2];
    const float m  = fmaxf(l0, fmaxf(l1, l2));
    const float e0 = expf(l0 - m), e1 = expf(l1 - m), e2 = expf(l2 - m);
    const float inv = 1.f / (e0 + e1 + e2);

    const bool use_pat = matched && (plog >= 0.f);  // p>=0.5 <=> logit>=0

    float o0, o1, o2;
    if (use_pat) {
        o0 = p;
        o1 = 0.5f * (1.f - p);
        o2 = o1;
    } else {
        o0 = e0 * inv;
        o1 = e1 * inv;
        o2 = e2 * inv;
    }
    out[b * 3 + 0] = o0;
    out[b * 3 + 1] = o1;
    out[b * 3 + 2] = o2;
}

// ---------------------------------------------------------------------------
extern "C" void kernel_launch(void* const* d_in, const int* in_sizes, int n_in,
                              void* d_out, int out_size) {
    const float* in      = (const float*)d_in[0];
    const float* conv_w  = (const float*)d_in[1];
    const float* conv_b  = (const float*)d_in[2];
    const float* match_w = (const float*)d_in[3];
    const float* match_b = (const float*)d_in[4];
    const float* pat_w   = (const float*)d_in[5];
    const float* pat_b   = (const float*)d_in[6];
    const float* base_w  = (const float*)d_in[7];
    const float* base_b  = (const float*)d_in[8];
    const int*   psi     = (const int*)d_in[9];

    prep_kernel<<<1024, 128>>>(base_w, pat_w, psi);
    main_kernel<<<dim3(8, 64), 128>>>(in, conv_w, conv_b, match_w);
    finalize_kernel<<<1, 256>>>(match_b, pat_b, base_b, (float*)d_out);
}